// round 13
// baseline (speedup 1.0000x reference)
#include <cuda_runtime.h>
#include <cuda_bf16.h>
#include <cuda_fp16.h>
#include <cstdint>
#include <math.h>

// ===========================================================================
// MultiScaleBlock (sm_103 PTX, HMMA mma.sync path).
// All GEMMs fp16 x1 (fused proj+qkv with maxpool epilogue; attn-proj; mlp).
// Attention: flash-style HMMA (m16n8k16) with fragment softmax.
// ===========================================================================

#define NPIX   (4*256*256)     // 262144
#define NPOOL  (4*128*128)     // 65536
#define NWIN   (4*32*32)       // 4096

// ---------------- scratch (device globals) ----------------------------------
__device__ __half g_x16 [(size_t)NPIX  * 96];    // LN1 out, window-major fp16
__device__ __half g_qkv [(size_t)NPIX  * 576];   // qkv fp16, window-major
__device__ __half g_o   [(size_t)NPOOL * 192];   // attention O
__device__ __half g_yn  [(size_t)NPOOL * 192];   // LN2 out
__device__ __half g_h   [(size_t)NPOOL * 768];   // mlp hidden
// weights fp16 [N][K] (transposed); proj+qkv fused into 768 rows
__device__ __half g_wf16[768*96];
__device__ __half g_wa16[192*192];
__device__ __half g_w116[768*192];
__device__ __half g_w216[192*768];
__device__ float  g_b768[768];

// ---------------- helpers ---------------------------------------------------
__device__ __forceinline__ uint32_t smem_u32(const void* p) {
    uint32_t a;
    asm("{ .reg .u64 t; cvta.to.shared.u64 t, %1; cvt.u32.u64 %0, t; }"
        : "=r"(a) : "l"(p));
    return a;
}
__device__ __forceinline__ void cp16(uint32_t s, const void* g) {
    asm volatile("cp.async.ca.shared.global [%0], [%1], 16;"
                 :: "r"(s), "l"(g) : "memory");
}
__device__ __forceinline__ void cp_commit() {
    asm volatile("cp.async.commit_group;" ::: "memory");
}
template<int N>
__device__ __forceinline__ void cp_wait() {
    asm volatile("cp.async.wait_group %0;" :: "n"(N) : "memory");
}
__device__ __forceinline__ void ldsm4(uint32_t* r, uint32_t a) {
    asm volatile("ldmatrix.sync.aligned.m8n8.x4.shared.b16 {%0,%1,%2,%3}, [%4];"
        : "=r"(r[0]), "=r"(r[1]), "=r"(r[2]), "=r"(r[3]) : "r"(a));
}
__device__ __forceinline__ void mma_fp16(float* d, const uint32_t* a,
                                         uint32_t b0, uint32_t b1) {
    asm volatile(
        "mma.sync.aligned.m16n8k16.row.col.f32.f16.f16.f32 "
        "{%0,%1,%2,%3}, {%4,%5,%6,%7}, {%8,%9}, {%0,%1,%2,%3};"
        : "+f"(d[0]), "+f"(d[1]), "+f"(d[2]), "+f"(d[3])
        : "r"(a[0]), "r"(a[1]), "r"(a[2]), "r"(a[3]), "r"(b0), "r"(b1));
}
__device__ __forceinline__ float gelu_exact(float v) {
    return 0.5f * v * (1.0f + erff(v * 0.70710678118654752f));
}
__device__ __forceinline__ size_t quad_to_prow(size_t g) {
    int t2 = (int)(g & 15);
    int wj = (int)((g >> 4) & 31);
    int wi = (int)((g >> 9) & 31);
    int b  = (int)(g >> 14);
    return ((size_t)(b * 128 + wi * 4 + (t2 >> 2))) * 128 + wj * 4 + (t2 & 3);
}

// ======== fp16 x1 GEMM, BM=128 BN=192 BK=32, 3-stage, 2 CTA/SM ==============
#define LDAH     40
#define SAH      0
#define SBH      (128*LDAH*2)               // 10240
#define STAGEH   (SBH + 192*LDAH*2)         // 25600
#define GEMMH_SMEM (3*STAGEH)               // 76800

__global__ __launch_bounds__(256, 2) void gemm_f16(
    const __half* __restrict__ A, const __half* __restrict__ B,
    int K, int N, int epi,
    const float* __restrict__ bias,
    float* __restrict__ Cf, __half* __restrict__ Ch,
    const float* __restrict__ addsrc)
{
    extern __shared__ char smem[];
    const uint32_t sb = smem_u32(smem);
    const int tid = threadIdx.x, lane = tid & 31, warp = tid >> 5;
    const int wm = (warp >> 1) * 32;
    const int wn = (warp & 1) * 96;
    const size_t bm = (size_t)blockIdx.y * 128;
    const size_t bn = (size_t)blockIdx.x * 192;
    const int C = K >> 5;

    const __half* AB = A + bm * K;
    const __half* BB = B + bn * K;

    float acc[2][12][4];
    #pragma unroll
    for (int i = 0; i < 2; i++)
        #pragma unroll
        for (int j = 0; j < 12; j++)
            #pragma unroll
            for (int q = 0; q < 4; q++) acc[i][j][q] = 0.f;

    auto load_stage = [&](int s, int c) {
        const uint32_t st = sb + (uint32_t)s * STAGEH;
        const size_t k0 = (size_t)c * 32;
        #pragma unroll
        for (int i = tid; i < 512; i += 256) {
            int r = i >> 2, q = i & 3;
            cp16(st + SAH + (uint32_t)(r * LDAH + q * 8) * 2,
                 AB + (size_t)r * K + k0 + q * 8);
        }
        #pragma unroll
        for (int i = tid; i < 768; i += 256) {
            int r = i >> 2, q = i & 3;
            cp16(st + SBH + (uint32_t)(r * LDAH + q * 8) * 2,
                 BB + (size_t)r * K + k0 + q * 8);
        }
        cp_commit();
    };

    auto compute_stage = [&](int s) {
        const uint32_t st = sb + (uint32_t)s * STAGEH;
        #pragma unroll
        for (int k16 = 0; k16 < 2; k16++) {
            uint32_t ah[2][4];
            #pragma unroll
            for (int mi = 0; mi < 2; mi++) {
                int row = wm + mi * 16 + (lane & 15);
                int col = k16 * 16 + (lane >> 4) * 8;
                ldsm4(ah[mi], st + SAH + (uint32_t)(row * LDAH + col) * 2);
            }
            #pragma unroll
            for (int ng = 0; ng < 6; ng++) {
                uint32_t bh[4];
                int nr = wn + ng * 16 + (lane & 7) + ((lane >> 4) & 1) * 8;
                int bc = k16 * 16 + ((lane >> 3) & 1) * 8;
                ldsm4(bh, st + SBH + (uint32_t)(nr * LDAH + bc) * 2);
                #pragma unroll
                for (int mi = 0; mi < 2; mi++) {
                    #pragma unroll
                    for (int sub = 0; sub < 2; sub++)
                        mma_fp16(acc[mi][ng * 2 + sub], ah[mi], bh[2*sub], bh[2*sub+1]);
                }
            }
        }
    };

    load_stage(0, 0);
    load_stage(1, 1);
    for (int c = 0; c < C; c++) {
        if (c + 1 < C) { cp_wait<1>(); } else { cp_wait<0>(); }
        __syncthreads();
        if (c + 2 < C) load_stage((c + 2) % 3, c + 2);
        compute_stage(c % 3);
        __syncthreads();
    }

    #pragma unroll
    for (int mi = 0; mi < 2; mi++) {
        #pragma unroll
        for (int nj = 0; nj < 12; nj++) {
            size_t row0 = bm + wm + mi * 16 + (lane >> 2);
            size_t col  = bn + wn + nj * 8 + 2 * (lane & 3);
            float b0 = bias[col], b1 = bias[col + 1];
            float v00 = acc[mi][nj][0] + b0, v01 = acc[mi][nj][1] + b1;
            float v10 = acc[mi][nj][2] + b0, v11 = acc[mi][nj][3] + b1;
            if (epi == 1) {
                v00 = gelu_exact(v00); v01 = gelu_exact(v01);
                v10 = gelu_exact(v10); v11 = gelu_exact(v11);
                *reinterpret_cast<__half2*>(Ch + row0 * N + col)       = __floats2half2_rn(v00, v01);
                *reinterpret_cast<__half2*>(Ch + (row0 + 8) * N + col) = __floats2half2_rn(v10, v11);
            } else if (epi == 2) {
                const float2 a0 = *reinterpret_cast<const float2*>(addsrc + row0 * N + col);
                const float2 a1 = *reinterpret_cast<const float2*>(addsrc + (row0 + 8) * N + col);
                *reinterpret_cast<float2*>(Cf + row0 * N + col)       = make_float2(v00 + a0.x, v01 + a0.y);
                *reinterpret_cast<float2*>(Cf + (row0 + 8) * N + col) = make_float2(v10 + a1.x, v11 + a1.y);
            } else {  // epi == 3
                if (bn == 0) {
                    float p00 = fmaxf(v00, __shfl_xor_sync(0xffffffffu, v00, 4));
                    p00 = fmaxf(p00, __shfl_xor_sync(0xffffffffu, p00, 8));
                    float p01 = fmaxf(v01, __shfl_xor_sync(0xffffffffu, v01, 4));
                    p01 = fmaxf(p01, __shfl_xor_sync(0xffffffffu, p01, 8));
                    float p10 = fmaxf(v10, __shfl_xor_sync(0xffffffffu, v10, 4));
                    p10 = fmaxf(p10, __shfl_xor_sync(0xffffffffu, p10, 8));
                    float p11 = fmaxf(v11, __shfl_xor_sync(0xffffffffu, v11, 4));
                    p11 = fmaxf(p11, __shfl_xor_sync(0xffffffffu, p11, 8));
                    if ((lane & 12) == 0) {
                        size_t pr0 = quad_to_prow(row0 >> 2);
                        size_t pr1 = quad_to_prow((row0 + 8) >> 2);
                        *reinterpret_cast<float2*>(Cf + pr0 * 192 + col) = make_float2(p00, p01);
                        *reinterpret_cast<float2*>(Cf + pr1 * 192 + col) = make_float2(p10, p11);
                    }
                } else {
                    size_t qc = col - 192;
                    *reinterpret_cast<__half2*>(Ch + row0 * 576 + qc)       = __floats2half2_rn(v00, v01);
                    *reinterpret_cast<__half2*>(Ch + (row0 + 8) * 576 + qc) = __floats2half2_rn(v10, v11);
                }
            }
        }
    }
}

// ---------------- LN1 -> fp16, window-major permuted rows -------------------
__global__ __launch_bounds__(256) void ln96h_kernel(
    const float* __restrict__ x, const float* __restrict__ g,
    const float* __restrict__ bb, __half* __restrict__ out)
{
    int row  = blockIdx.x * 8 + (threadIdx.x >> 5);
    int lane = threadIdx.x & 31;
    const float* p = x + (size_t)row * 96;
    float v0 = p[lane], v1 = p[lane+32], v2 = p[lane+64];
    float s = v0 + v1 + v2;
    #pragma unroll
    for (int o = 16; o > 0; o >>= 1) s += __shfl_xor_sync(0xffffffffu, s, o);
    float mean = s * (1.0f/96.0f);
    float d0 = v0-mean, d1 = v1-mean, d2 = v2-mean;
    float vs = d0*d0 + d1*d1 + d2*d2;
    #pragma unroll
    for (int o = 16; o > 0; o >>= 1) vs += __shfl_xor_sync(0xffffffffu, vs, o);
    float inv = rsqrtf(vs * (1.0f/96.0f) + 1e-6f);
    int wpix = row & 255, hpix = (row >> 8) & 255, b = row >> 16;
    int wi = hpix >> 3, r = hpix & 7, wj = wpix >> 3, c = wpix & 7;
    int t2 = (r >> 1) * 4 + (c >> 1);
    int dq = (r & 1) * 2 + (c & 1);
    size_t wrow = ((((size_t)b * 32 + wi) * 32 + wj) * 16 + t2) * 4 + dq;
    __half* q = out + wrow * 96;
    q[lane]    = __float2half(d0*inv*g[lane]    + bb[lane]);
    q[lane+32] = __float2half(d1*inv*g[lane+32] + bb[lane+32]);
    q[lane+64] = __float2half(d2*inv*g[lane+64] + bb[lane+64]);
}

// ---------------- LN2 -> fp16 -----------------------------------------------
__global__ __launch_bounds__(256) void ln192h_kernel(
    const float* __restrict__ x, const float* __restrict__ g,
    const float* __restrict__ bb, __half* __restrict__ out)
{
    int row  = blockIdx.x * 8 + (threadIdx.x >> 5);
    int lane = threadIdx.x & 31;
    const float* p = x + (size_t)row * 192;
    float v[6];
    float s = 0.f;
    #pragma unroll
    for (int i = 0; i < 6; i++) { v[i] = p[lane + 32*i]; s += v[i]; }
    #pragma unroll
    for (int o = 16; o > 0; o >>= 1) s += __shfl_xor_sync(0xffffffffu, s, o);
    float mean = s * (1.0f/192.0f);
    float vs = 0.f;
    #pragma unroll
    for (int i = 0; i < 6; i++) { v[i] -= mean; vs += v[i]*v[i]; }
    #pragma unroll
    for (int o = 16; o > 0; o >>= 1) vs += __shfl_xor_sync(0xffffffffu, vs, o);
    float inv = rsqrtf(vs * (1.0f/192.0f) + 1e-6f);
    __half* q = out + (size_t)row * 192;
    #pragma unroll
    for (int i = 0; i < 6; i++)
        q[lane + 32*i] = __float2half(v[i]*inv*g[lane + 32*i] + bb[lane + 32*i]);
}

// ---------------- merged weight conversion + bias concat --------------------
__global__ __launch_bounds__(256) void conv_all_kernel(
    const float* __restrict__ proj_w, const float* __restrict__ qkv_w,
    const float* __restrict__ apw, const float* __restrict__ w1,
    const float* __restrict__ w2,
    const float* __restrict__ proj_b, const float* __restrict__ qkv_b,
    __half* __restrict__ wf16, __half* __restrict__ wa16,
    __half* __restrict__ w116, __half* __restrict__ w216,
    float* __restrict__ b768)
{
    int i = blockIdx.x * 256 + threadIdx.x;
    if (i < 405504) {
        const float* W; __half* H; int K, N, j;
        if (i < 18432)       { W = proj_w; H = wf16;         K = 96;  N = 192; j = i; }
        else if (i < 73728)  { W = qkv_w;  H = wf16 + 18432; K = 96;  N = 576; j = i - 18432; }
        else if (i < 110592) { W = apw;    H = wa16;         K = 192; N = 192; j = i - 73728; }
        else if (i < 258048) { W = w1;     H = w116;         K = 192; N = 768; j = i - 110592; }
        else                 { W = w2;     H = w216;         K = 768; N = 192; j = i - 258048; }
        int n = j / K, k = j % K;
        H[j] = __float2half(W[(size_t)k * N + n]);
    } else if (i < 406272) {
        int j = i - 405504;
        b768[j] = (j < 192) ? proj_b[j] : qkv_b[j - 192];
    }
}

// ---------------- flash-style HMMA windowed attention -----------------------
// One 128-thread CTA per window; warps 0-2 = heads, warp 3 loads only.
// smem (halves): qp [16][200] @0 | kh [64][200] @3200 | vh(V^T) [192][72] @16000
#define QP_OFF  0
#define KH_OFF  3200
#define VH_OFF  16000
#define ATT_SMEM 59648          // 29824 halves

__global__ __launch_bounds__(128, 3) void attn_kernel(
    const __half* __restrict__ qkv, __half* __restrict__ O)
{
    extern __shared__ char smem[];
    const uint32_t sb = smem_u32(smem);
    uint32_t* smw = reinterpret_cast<uint32_t*>(smem);

    int w = blockIdx.x;
    int b = w >> 10, wi = (w >> 5) & 31, wj = w & 31;
    int tid = threadIdx.x;
    const uint32_t* qk = reinterpret_cast<const uint32_t*>(qkv + (size_t)w * 64 * 576);

    // ---- load phase (all 128 threads) ----
    // pooled q (max over 4 quad rows), fp16x2 words -> qp[t2][c2]
    for (int i = tid; i < 16*96; i += 128) {
        int t2 = i / 96, c2 = i % 96;
        float m0 = -1e30f, m1 = -1e30f;
        #pragma unroll
        for (int dq = 0; dq < 4; dq++) {
            uint32_t wd = qk[(t2*4 + dq)*288 + c2];
            float2 v = __half22float2(*reinterpret_cast<__half2*>(&wd));
            m0 = fmaxf(m0, v.x);
            m1 = fmaxf(m1, v.y);
        }
        __half2 r = __floats2half2_rn(m0, m1);
        smw[(QP_OFF >> 1) + t2*100 + c2] = *reinterpret_cast<uint32_t*>(&r);
    }
    // k rows direct copy (uint4): kh[s][0..191]
    {
        const uint4* qk4 = reinterpret_cast<const uint4*>(qk);
        for (int i = tid; i < 64*24; i += 128) {
            int s = i / 24, c4 = i % 24;
            uint4 v = qk4[s*72 + 24 + c4];
            uint32_t d = sb + (uint32_t)(KH_OFF + s*200)*2 + c4*16;
            asm volatile("st.shared.v4.b32 [%0], {%1,%2,%3,%4};"
                :: "r"(d), "r"(v.x), "r"(v.y), "r"(v.z), "r"(v.w));
        }
    }
    // v transposed: vh[d][s]
    {
        __half* vh = reinterpret_cast<__half*>(smem) + VH_OFF;
        for (int i = tid; i < 64*96; i += 128) {
            int d2 = i % 96, s = i / 96;
            uint32_t vw = qk[s*288 + 192 + d2];
            __half2 vv = *reinterpret_cast<__half2*>(&vw);
            vh[(d2*2    )*72 + s] = vv.x;
            vh[(d2*2 + 1)*72 + s] = vv.y;
        }
    }
    __syncthreads();

    const int warp = tid >> 5, lane = tid & 31;
    if (warp < 3) {
        const int h = warp;
        // ---- S = Qp . K^T  (16 x 64), fp32 accum ----
        float sacc[8][4];
        #pragma unroll
        for (int j = 0; j < 8; j++)
            #pragma unroll
            for (int q = 0; q < 4; q++) sacc[j][q] = 0.f;

        #pragma unroll
        for (int kk = 0; kk < 4; kk++) {
            uint32_t aq[4];
            ldsm4(aq, sb + (uint32_t)(QP_OFF + (lane & 15)*200 + h*64 + kk*16 + (lane >> 4)*8)*2);
            #pragma unroll
            for (int ng = 0; ng < 4; ng++) {
                uint32_t bk[4];
                int nr = ng*16 + (lane & 7) + ((lane >> 4) & 1)*8;
                int bc = h*64 + kk*16 + ((lane >> 3) & 1)*8;
                ldsm4(bk, sb + (uint32_t)(KH_OFF + nr*200 + bc)*2);
                mma_fp16(sacc[2*ng],     aq, bk[0], bk[1]);
                mma_fp16(sacc[2*ng + 1], aq, bk[2], bk[3]);
            }
        }

        // ---- fragment softmax (rows g=lane>>2 and g+8; 4 lanes per row) ----
        float mx0 = -1e30f, mx1 = -1e30f;
        #pragma unroll
        for (int j = 0; j < 8; j++) {
            mx0 = fmaxf(mx0, fmaxf(sacc[j][0], sacc[j][1]));
            mx1 = fmaxf(mx1, fmaxf(sacc[j][2], sacc[j][3]));
        }
        #pragma unroll
        for (int o = 1; o < 4; o <<= 1) {
            mx0 = fmaxf(mx0, __shfl_xor_sync(0xffffffffu, mx0, o));
            mx1 = fmaxf(mx1, __shfl_xor_sync(0xffffffffu, mx1, o));
        }
        float l0 = 0.f, l1 = 0.f;
        #pragma unroll
        for (int j = 0; j < 8; j++) {
            sacc[j][0] = __expf((sacc[j][0] - mx0) * 0.125f);
            sacc[j][1] = __expf((sacc[j][1] - mx0) * 0.125f);
            sacc[j][2] = __expf((sacc[j][2] - mx1) * 0.125f);
            sacc[j][3] = __expf((sacc[j][3] - mx1) * 0.125f);
            l0 += sacc[j][0] + sacc[j][1];
            l1 += sacc[j][2] + sacc[j][3];
        }
        #pragma unroll
        for (int o = 1; o < 4; o <<= 1) {
            l0 += __shfl_xor_sync(0xffffffffu, l0, o);
            l1 += __shfl_xor_sync(0xffffffffu, l1, o);
        }
        float inv0 = 1.f / l0, inv1 = 1.f / l1;

        // ---- O = P . V (reuse C fragments as A fragments) ----
        float oacc[8][4];
        #pragma unroll
        for (int j = 0; j < 8; j++)
            #pragma unroll
            for (int q = 0; q < 4; q++) oacc[j][q] = 0.f;

        #pragma unroll
        for (int ss = 0; ss < 4; ss++) {
            uint32_t pa[4];
            {
                __half2 h0 = __floats2half2_rn(sacc[2*ss][0]*inv0,   sacc[2*ss][1]*inv0);
                __half2 h1 = __floats2half2_rn(sacc[2*ss][2]*inv1,   sacc[2*ss][3]*inv1);
                __half2 h2 = __floats2half2_rn(sacc[2*ss+1][0]*inv0, sacc[2*ss+1][1]*inv0);
                __half2 h3 = __floats2half2_rn(sacc[2*ss+1][2]*inv1, sacc[2*ss+1][3]*inv1);
                pa[0] = *reinterpret_cast<uint32_t*>(&h0);
                pa[1] = *reinterpret_cast<uint32_t*>(&h1);
                pa[2] = *reinterpret_cast<uint32_t*>(&h2);
                pa[3] = *reinterpret_cast<uint32_t*>(&h3);
            }
            #pragma unroll
            for (int ng = 0; ng < 4; ng++) {
                uint32_t bv[4];
                int nr = h*64 + ng*16 + (lane & 7) + ((lane >> 4) & 1)*8;
                int bc = ss*16 + ((lane >> 3) & 1)*8;
                ldsm4(bv, sb + (uint32_t)(VH_OFF + nr*72 + bc)*2);
                mma_fp16(oacc[2*ng],     pa, bv[0], bv[1]);
                mma_fp16(oacc[2*ng + 1], pa, bv[2], bv[3]);
            }
        }

        // ---- store O fragments ----
        int g = lane >> 2, t = lane & 3;
        int r0 = g, r1 = g + 8;
        size_t orow0 = ((size_t)(b*128 + wi*4 + (r0 >> 2)))*128 + wj*4 + (r0 & 3);
        size_t orow1 = ((size_t)(b*128 + wi*4 + (r1 >> 2)))*128 + wj*4 + (r1 & 3);
        #pragma unroll
        for (int j = 0; j < 8; j++) {
            int col = h*64 + j*8 + 2*t;
            *reinterpret_cast<__half2*>(O + orow0*192 + col) =
                __floats2half2_rn(oacc[j][0], oacc[j][1]);
            *reinterpret_cast<__half2*>(O + orow1*192 + col) =
                __floats2half2_rn(oacc[j][2], oacc[j][3]);
        }
    }
}

// ---------------- launch ----------------------------------------------------
extern "C" void kernel_launch(void* const* d_in, const int* in_sizes, int n_in,
                              void* d_out, int out_size)
{
    const float* x       = (const float*)d_in[0];
    const float* n1g     = (const float*)d_in[1];
    const float* n1b     = (const float*)d_in[2];
    const float* proj_w  = (const float*)d_in[3];
    const float* proj_b  = (const float*)d_in[4];
    const float* qkv_w   = (const float*)d_in[5];
    const float* qkv_b   = (const float*)d_in[6];
    const float* apw     = (const float*)d_in[7];
    const float* apb     = (const float*)d_in[8];
    const float* n2g     = (const float*)d_in[9];
    const float* n2b     = (const float*)d_in[10];
    const float* w1      = (const float*)d_in[11];
    const float* b1      = (const float*)d_in[12];
    const float* w2      = (const float*)d_in[13];
    const float* b2      = (const float*)d_in[14];
    float* y = (float*)d_out;

    __half *x16, *qkv16, *o16, *yn16, *h16, *wf16, *wa16, *w116, *w216;
    float *b768;
    cudaGetSymbolAddress((void**)&x16,  g_x16);
    cudaGetSymbolAddress((void**)&qkv16, g_qkv);
    cudaGetSymbolAddress((void**)&o16,  g_o);
    cudaGetSymbolAddress((void**)&yn16, g_yn);
    cudaGetSymbolAddress((void**)&h16,  g_h);
    cudaGetSymbolAddress((void**)&wf16, g_wf16);
    cudaGetSymbolAddress((void**)&wa16, g_wa16);
    cudaGetSymbolAddress((void**)&w116, g_w116);
    cudaGetSymbolAddress((void**)&w216, g_w216);
    cudaGetSymbolAddress((void**)&b768, g_b768);

    static bool attr_done = false;
    if (!attr_done) {
        cudaFuncSetAttribute(attn_kernel,
            cudaFuncAttributeMaxDynamicSharedMemorySize, ATT_SMEM);
        cudaFuncSetAttribute(gemm_f16,
            cudaFuncAttributeMaxDynamicSharedMemorySize, GEMMH_SMEM);
        attr_done = true;
    }

    // 0) merged weight conversions + bias concat
    conv_all_kernel<<<(406272 + 255) / 256, 256>>>(
        proj_w, qkv_w, apw, w1, w2, proj_b, qkv_b,
        wf16, wa16, w116, w216, b768);
    // 1) LN1 -> fp16 (window-major rows)
    ln96h_kernel<<<NPIX/8, 256>>>(x, n1g, n1b, x16);
    // 2) fused proj+qkv GEMM: tile0 -> pooled y, tiles1-3 -> qkv fp16
    gemm_f16<<<dim3(4, NPIX/128), 256, GEMMH_SMEM>>>(
        x16, wf16, 96, 768, 3, b768, y, qkv16, nullptr);
    // 3) windowed attention (HMMA flash) -> O (fp16)
    attn_kernel<<<NWIN, 128, ATT_SMEM>>>(qkv16, o16);
    // 4) attn-proj GEMM: y += O @ apw + apb
    gemm_f16<<<dim3(1, NPOOL/128), 256, GEMMH_SMEM>>>(
        o16, wa16, 192, 192, 2, apb, y, nullptr, y);
    // 5) LN2 -> fp16
    ln192h_kernel<<<NPOOL/8, 256>>>(y, n2g, n2b, yn16);
    // 6) mlp1 GEMM + gelu -> h (fp16)
    gemm_f16<<<dim3(4, NPOOL/128), 256, GEMMH_SMEM>>>(
        yn16, w116, 192, 768, 1, b1, nullptr, h16, nullptr);
    // 7) mlp2 GEMM + residual add -> y (d_out)
    gemm_f16<<<dim3(1, NPOOL/128), 256, GEMMH_SMEM>>>(
        h16, w216, 768, 192, 2, b2, y, nullptr, y);
}

// round 14
// speedup vs baseline: 1.1691x; 1.1691x over previous
#include <cuda_runtime.h>
#include <cuda_bf16.h>
#include <cuda_fp16.h>
#include <cstdint>
#include <math.h>

// ===========================================================================
// MultiScaleBlock (sm_103 PTX, HMMA mma.sync path).
// All GEMMs fp16 x1 (fused proj+qkv with maxpool epilogue; attn-proj; mlp).
// Attention: flash-style HMMA, cp.async K|V block, ldmatrix.trans for V,
// 4 CTAs/SM.
// ===========================================================================

#define NPIX   (4*256*256)     // 262144
#define NPOOL  (4*128*128)     // 65536
#define NWIN   (4*32*32)       // 4096

// ---------------- scratch (device globals) ----------------------------------
__device__ __half g_x16 [(size_t)NPIX  * 96];    // LN1 out, window-major fp16
__device__ __half g_qkv [(size_t)NPIX  * 576];   // qkv fp16, window-major
__device__ __half g_o   [(size_t)NPOOL * 192];   // attention O
__device__ __half g_yn  [(size_t)NPOOL * 192];   // LN2 out
__device__ __half g_h   [(size_t)NPOOL * 768];   // mlp hidden
// weights fp16 [N][K] (transposed); proj+qkv fused into 768 rows
__device__ __half g_wf16[768*96];
__device__ __half g_wa16[192*192];
__device__ __half g_w116[768*192];
__device__ __half g_w216[192*768];
__device__ float  g_b768[768];

// ---------------- helpers ---------------------------------------------------
__device__ __forceinline__ uint32_t smem_u32(const void* p) {
    uint32_t a;
    asm("{ .reg .u64 t; cvta.to.shared.u64 t, %1; cvt.u32.u64 %0, t; }"
        : "=r"(a) : "l"(p));
    return a;
}
__device__ __forceinline__ void cp16(uint32_t s, const void* g) {
    asm volatile("cp.async.ca.shared.global [%0], [%1], 16;"
                 :: "r"(s), "l"(g) : "memory");
}
__device__ __forceinline__ void cp_commit() {
    asm volatile("cp.async.commit_group;" ::: "memory");
}
template<int N>
__device__ __forceinline__ void cp_wait() {
    asm volatile("cp.async.wait_group %0;" :: "n"(N) : "memory");
}
__device__ __forceinline__ void ldsm4(uint32_t* r, uint32_t a) {
    asm volatile("ldmatrix.sync.aligned.m8n8.x4.shared.b16 {%0,%1,%2,%3}, [%4];"
        : "=r"(r[0]), "=r"(r[1]), "=r"(r[2]), "=r"(r[3]) : "r"(a));
}
__device__ __forceinline__ void ldsm4t(uint32_t* r, uint32_t a) {
    asm volatile("ldmatrix.sync.aligned.m8n8.x4.trans.shared.b16 {%0,%1,%2,%3}, [%4];"
        : "=r"(r[0]), "=r"(r[1]), "=r"(r[2]), "=r"(r[3]) : "r"(a));
}
__device__ __forceinline__ void mma_fp16(float* d, const uint32_t* a,
                                         uint32_t b0, uint32_t b1) {
    asm volatile(
        "mma.sync.aligned.m16n8k16.row.col.f32.f16.f16.f32 "
        "{%0,%1,%2,%3}, {%4,%5,%6,%7}, {%8,%9}, {%0,%1,%2,%3};"
        : "+f"(d[0]), "+f"(d[1]), "+f"(d[2]), "+f"(d[3])
        : "r"(a[0]), "r"(a[1]), "r"(a[2]), "r"(a[3]), "r"(b0), "r"(b1));
}
__device__ __forceinline__ float gelu_exact(float v) {
    return 0.5f * v * (1.0f + erff(v * 0.70710678118654752f));
}
__device__ __forceinline__ size_t quad_to_prow(size_t g) {
    int t2 = (int)(g & 15);
    int wj = (int)((g >> 4) & 31);
    int wi = (int)((g >> 9) & 31);
    int b  = (int)(g >> 14);
    return ((size_t)(b * 128 + wi * 4 + (t2 >> 2))) * 128 + wj * 4 + (t2 & 3);
}

// ======== fp16 x1 GEMM, BM=128 BN=192 BK=32, 3-stage, 2 CTA/SM ==============
#define LDAH     40
#define SAH      0
#define SBH      (128*LDAH*2)               // 10240
#define STAGEH   (SBH + 192*LDAH*2)         // 25600
#define GEMMH_SMEM (3*STAGEH)               // 76800

__global__ __launch_bounds__(256, 2) void gemm_f16(
    const __half* __restrict__ A, const __half* __restrict__ B,
    int K, int N, int epi,
    const float* __restrict__ bias,
    float* __restrict__ Cf, __half* __restrict__ Ch,
    const float* __restrict__ addsrc)
{
    extern __shared__ char smem[];
    const uint32_t sb = smem_u32(smem);
    const int tid = threadIdx.x, lane = tid & 31, warp = tid >> 5;
    const int wm = (warp >> 1) * 32;
    const int wn = (warp & 1) * 96;
    const size_t bm = (size_t)blockIdx.y * 128;
    const size_t bn = (size_t)blockIdx.x * 192;
    const int C = K >> 5;

    const __half* AB = A + bm * K;
    const __half* BB = B + bn * K;

    float acc[2][12][4];
    #pragma unroll
    for (int i = 0; i < 2; i++)
        #pragma unroll
        for (int j = 0; j < 12; j++)
            #pragma unroll
            for (int q = 0; q < 4; q++) acc[i][j][q] = 0.f;

    auto load_stage = [&](int s, int c) {
        const uint32_t st = sb + (uint32_t)s * STAGEH;
        const size_t k0 = (size_t)c * 32;
        #pragma unroll
        for (int i = tid; i < 512; i += 256) {
            int r = i >> 2, q = i & 3;
            cp16(st + SAH + (uint32_t)(r * LDAH + q * 8) * 2,
                 AB + (size_t)r * K + k0 + q * 8);
        }
        #pragma unroll
        for (int i = tid; i < 768; i += 256) {
            int r = i >> 2, q = i & 3;
            cp16(st + SBH + (uint32_t)(r * LDAH + q * 8) * 2,
                 BB + (size_t)r * K + k0 + q * 8);
        }
        cp_commit();
    };

    auto compute_stage = [&](int s) {
        const uint32_t st = sb + (uint32_t)s * STAGEH;
        #pragma unroll
        for (int k16 = 0; k16 < 2; k16++) {
            uint32_t ah[2][4];
            #pragma unroll
            for (int mi = 0; mi < 2; mi++) {
                int row = wm + mi * 16 + (lane & 15);
                int col = k16 * 16 + (lane >> 4) * 8;
                ldsm4(ah[mi], st + SAH + (uint32_t)(row * LDAH + col) * 2);
            }
            #pragma unroll
            for (int ng = 0; ng < 6; ng++) {
                uint32_t bh[4];
                int nr = wn + ng * 16 + (lane & 7) + ((lane >> 4) & 1) * 8;
                int bc = k16 * 16 + ((lane >> 3) & 1) * 8;
                ldsm4(bh, st + SBH + (uint32_t)(nr * LDAH + bc) * 2);
                #pragma unroll
                for (int mi = 0; mi < 2; mi++) {
                    #pragma unroll
                    for (int sub = 0; sub < 2; sub++)
                        mma_fp16(acc[mi][ng * 2 + sub], ah[mi], bh[2*sub], bh[2*sub+1]);
                }
            }
        }
    };

    load_stage(0, 0);
    load_stage(1, 1);
    for (int c = 0; c < C; c++) {
        if (c + 1 < C) { cp_wait<1>(); } else { cp_wait<0>(); }
        __syncthreads();
        if (c + 2 < C) load_stage((c + 2) % 3, c + 2);
        compute_stage(c % 3);
        __syncthreads();
    }

    #pragma unroll
    for (int mi = 0; mi < 2; mi++) {
        #pragma unroll
        for (int nj = 0; nj < 12; nj++) {
            size_t row0 = bm + wm + mi * 16 + (lane >> 2);
            size_t col  = bn + wn + nj * 8 + 2 * (lane & 3);
            float b0 = bias[col], b1 = bias[col + 1];
            float v00 = acc[mi][nj][0] + b0, v01 = acc[mi][nj][1] + b1;
            float v10 = acc[mi][nj][2] + b0, v11 = acc[mi][nj][3] + b1;
            if (epi == 1) {
                v00 = gelu_exact(v00); v01 = gelu_exact(v01);
                v10 = gelu_exact(v10); v11 = gelu_exact(v11);
                *reinterpret_cast<__half2*>(Ch + row0 * N + col)       = __floats2half2_rn(v00, v01);
                *reinterpret_cast<__half2*>(Ch + (row0 + 8) * N + col) = __floats2half2_rn(v10, v11);
            } else if (epi == 2) {
                const float2 a0 = *reinterpret_cast<const float2*>(addsrc + row0 * N + col);
                const float2 a1 = *reinterpret_cast<const float2*>(addsrc + (row0 + 8) * N + col);
                *reinterpret_cast<float2*>(Cf + row0 * N + col)       = make_float2(v00 + a0.x, v01 + a0.y);
                *reinterpret_cast<float2*>(Cf + (row0 + 8) * N + col) = make_float2(v10 + a1.x, v11 + a1.y);
            } else {  // epi == 3
                if (bn == 0) {
                    float p00 = fmaxf(v00, __shfl_xor_sync(0xffffffffu, v00, 4));
                    p00 = fmaxf(p00, __shfl_xor_sync(0xffffffffu, p00, 8));
                    float p01 = fmaxf(v01, __shfl_xor_sync(0xffffffffu, v01, 4));
                    p01 = fmaxf(p01, __shfl_xor_sync(0xffffffffu, p01, 8));
                    float p10 = fmaxf(v10, __shfl_xor_sync(0xffffffffu, v10, 4));
                    p10 = fmaxf(p10, __shfl_xor_sync(0xffffffffu, p10, 8));
                    float p11 = fmaxf(v11, __shfl_xor_sync(0xffffffffu, v11, 4));
                    p11 = fmaxf(p11, __shfl_xor_sync(0xffffffffu, p11, 8));
                    if ((lane & 12) == 0) {
                        size_t pr0 = quad_to_prow(row0 >> 2);
                        size_t pr1 = quad_to_prow((row0 + 8) >> 2);
                        *reinterpret_cast<float2*>(Cf + pr0 * 192 + col) = make_float2(p00, p01);
                        *reinterpret_cast<float2*>(Cf + pr1 * 192 + col) = make_float2(p10, p11);
                    }
                } else {
                    size_t qc = col - 192;
                    *reinterpret_cast<__half2*>(Ch + row0 * 576 + qc)       = __floats2half2_rn(v00, v01);
                    *reinterpret_cast<__half2*>(Ch + (row0 + 8) * 576 + qc) = __floats2half2_rn(v10, v11);
                }
            }
        }
    }
}

// ---------------- LN1 -> fp16, window-major permuted rows -------------------
__global__ __launch_bounds__(256) void ln96h_kernel(
    const float* __restrict__ x, const float* __restrict__ g,
    const float* __restrict__ bb, __half* __restrict__ out)
{
    int row  = blockIdx.x * 8 + (threadIdx.x >> 5);
    int lane = threadIdx.x & 31;
    const float* p = x + (size_t)row * 96;
    float v0 = p[lane], v1 = p[lane+32], v2 = p[lane+64];
    float s = v0 + v1 + v2;
    #pragma unroll
    for (int o = 16; o > 0; o >>= 1) s += __shfl_xor_sync(0xffffffffu, s, o);
    float mean = s * (1.0f/96.0f);
    float d0 = v0-mean, d1 = v1-mean, d2 = v2-mean;
    float vs = d0*d0 + d1*d1 + d2*d2;
    #pragma unroll
    for (int o = 16; o > 0; o >>= 1) vs += __shfl_xor_sync(0xffffffffu, vs, o);
    float inv = rsqrtf(vs * (1.0f/96.0f) + 1e-6f);
    int wpix = row & 255, hpix = (row >> 8) & 255, b = row >> 16;
    int wi = hpix >> 3, r = hpix & 7, wj = wpix >> 3, c = wpix & 7;
    int t2 = (r >> 1) * 4 + (c >> 1);
    int dq = (r & 1) * 2 + (c & 1);
    size_t wrow = ((((size_t)b * 32 + wi) * 32 + wj) * 16 + t2) * 4 + dq;
    __half* q = out + wrow * 96;
    q[lane]    = __float2half(d0*inv*g[lane]    + bb[lane]);
    q[lane+32] = __float2half(d1*inv*g[lane+32] + bb[lane+32]);
    q[lane+64] = __float2half(d2*inv*g[lane+64] + bb[lane+64]);
}

// ---------------- LN2 -> fp16 -----------------------------------------------
__global__ __launch_bounds__(256) void ln192h_kernel(
    const float* __restrict__ x, const float* __restrict__ g,
    const float* __restrict__ bb, __half* __restrict__ out)
{
    int row  = blockIdx.x * 8 + (threadIdx.x >> 5);
    int lane = threadIdx.x & 31;
    const float* p = x + (size_t)row * 192;
    float v[6];
    float s = 0.f;
    #pragma unroll
    for (int i = 0; i < 6; i++) { v[i] = p[lane + 32*i]; s += v[i]; }
    #pragma unroll
    for (int o = 16; o > 0; o >>= 1) s += __shfl_xor_sync(0xffffffffu, s, o);
    float mean = s * (1.0f/192.0f);
    float vs = 0.f;
    #pragma unroll
    for (int i = 0; i < 6; i++) { v[i] -= mean; vs += v[i]*v[i]; }
    #pragma unroll
    for (int o = 16; o > 0; o >>= 1) vs += __shfl_xor_sync(0xffffffffu, vs, o);
    float inv = rsqrtf(vs * (1.0f/192.0f) + 1e-6f);
    __half* q = out + (size_t)row * 192;
    #pragma unroll
    for (int i = 0; i < 6; i++)
        q[lane + 32*i] = __float2half(v[i]*inv*g[lane + 32*i] + bb[lane + 32*i]);
}

// ---------------- merged weight conversion + bias concat --------------------
__global__ __launch_bounds__(256) void conv_all_kernel(
    const float* __restrict__ proj_w, const float* __restrict__ qkv_w,
    const float* __restrict__ apw, const float* __restrict__ w1,
    const float* __restrict__ w2,
    const float* __restrict__ proj_b, const float* __restrict__ qkv_b,
    __half* __restrict__ wf16, __half* __restrict__ wa16,
    __half* __restrict__ w116, __half* __restrict__ w216,
    float* __restrict__ b768)
{
    int i = blockIdx.x * 256 + threadIdx.x;
    if (i < 405504) {
        const float* W; __half* H; int K, N, j;
        if (i < 18432)       { W = proj_w; H = wf16;         K = 96;  N = 192; j = i; }
        else if (i < 73728)  { W = qkv_w;  H = wf16 + 18432; K = 96;  N = 576; j = i - 18432; }
        else if (i < 110592) { W = apw;    H = wa16;         K = 192; N = 192; j = i - 73728; }
        else if (i < 258048) { W = w1;     H = w116;         K = 192; N = 768; j = i - 110592; }
        else                 { W = w2;     H = w216;         K = 768; N = 192; j = i - 258048; }
        int n = j / K, k = j % K;
        H[j] = __float2half(W[(size_t)k * N + n]);
    } else if (i < 406272) {
        int j = i - 405504;
        b768[j] = (j < 192) ? proj_b[j] : qkv_b[j - 192];
    }
}

// ---------------- flash HMMA windowed attention (cp.async kv) ---------------
// 128 threads/window, 4 CTAs/SM.
// smem (halves): qp [16][200] @0 | kv [64][392] @3200 (k 0..191 | v 192..383)
#define QP_OFF  0
#define KV_OFF  3200
#define KV_LD   392
#define ATT_SMEM ((3200 + 64*KV_LD) * 2)    // 56576 B

__global__ __launch_bounds__(128, 4) void attn_kernel(
    const __half* __restrict__ qkv, __half* __restrict__ O)
{
    extern __shared__ char smem[];
    const uint32_t sb = smem_u32(smem);
    uint32_t* smw = reinterpret_cast<uint32_t*>(smem);

    int w = blockIdx.x;
    int b = w >> 10, wi = (w >> 5) & 31, wj = w & 31;
    int tid = threadIdx.x;
    const __half* base = qkv + (size_t)w * 64 * 576;
    const uint32_t* qk = reinterpret_cast<const uint32_t*>(base);

    // ---- cp.async the K|V block: rows s, halves 192..575 -> kv[s][0..383] --
    for (int i = tid; i < 64*48; i += 128) {
        int s = i / 48, c = i % 48;
        cp16(sb + (uint32_t)(KV_OFF + s*KV_LD)*2 + c*16,
             base + (size_t)s*576 + 192 + c*8);
    }
    cp_commit();

    // ---- pooled q (max over 4 quad rows) while kv streams ----
    for (int i = tid; i < 16*96; i += 128) {
        int t2 = i / 96, c2 = i % 96;
        float m0 = -1e30f, m1 = -1e30f;
        #pragma unroll
        for (int dq = 0; dq < 4; dq++) {
            uint32_t wd = qk[(t2*4 + dq)*288 + c2];
            float2 v = __half22float2(*reinterpret_cast<__half2*>(&wd));
            m0 = fmaxf(m0, v.x);
            m1 = fmaxf(m1, v.y);
        }
        __half2 r = __floats2half2_rn(m0, m1);
        smw[(QP_OFF >> 1) + t2*100 + c2] = *reinterpret_cast<uint32_t*>(&r);
    }
    cp_wait<0>();
    __syncthreads();

    const int warp = tid >> 5, lane = tid & 31;
    if (warp < 3) {
        const int h = warp;
        // ---- S = Qp . K^T ----
        float sacc[8][4];
        #pragma unroll
        for (int j = 0; j < 8; j++)
            #pragma unroll
            for (int q = 0; q < 4; q++) sacc[j][q] = 0.f;

        #pragma unroll
        for (int kk = 0; kk < 4; kk++) {
            uint32_t aq[4];
            ldsm4(aq, sb + (uint32_t)(QP_OFF + (lane & 15)*200 + h*64 + kk*16 + (lane >> 4)*8)*2);
            #pragma unroll
            for (int ng = 0; ng < 4; ng++) {
                uint32_t bk[4];
                int nr = ng*16 + (lane & 7) + ((lane >> 4) & 1)*8;
                int bc = h*64 + kk*16 + ((lane >> 3) & 1)*8;
                ldsm4(bk, sb + (uint32_t)(KV_OFF + nr*KV_LD + bc)*2);
                mma_fp16(sacc[2*ng],     aq, bk[0], bk[1]);
                mma_fp16(sacc[2*ng + 1], aq, bk[2], bk[3]);
            }
        }

        // ---- fragment softmax ----
        float mx0 = -1e30f, mx1 = -1e30f;
        #pragma unroll
        for (int j = 0; j < 8; j++) {
            mx0 = fmaxf(mx0, fmaxf(sacc[j][0], sacc[j][1]));
            mx1 = fmaxf(mx1, fmaxf(sacc[j][2], sacc[j][3]));
        }
        #pragma unroll
        for (int o = 1; o < 4; o <<= 1) {
            mx0 = fmaxf(mx0, __shfl_xor_sync(0xffffffffu, mx0, o));
            mx1 = fmaxf(mx1, __shfl_xor_sync(0xffffffffu, mx1, o));
        }
        float l0 = 0.f, l1 = 0.f;
        #pragma unroll
        for (int j = 0; j < 8; j++) {
            sacc[j][0] = __expf((sacc[j][0] - mx0) * 0.125f);
            sacc[j][1] = __expf((sacc[j][1] - mx0) * 0.125f);
            sacc[j][2] = __expf((sacc[j][2] - mx1) * 0.125f);
            sacc[j][3] = __expf((sacc[j][3] - mx1) * 0.125f);
            l0 += sacc[j][0] + sacc[j][1];
            l1 += sacc[j][2] + sacc[j][3];
        }
        #pragma unroll
        for (int o = 1; o < 4; o <<= 1) {
            l0 += __shfl_xor_sync(0xffffffffu, l0, o);
            l1 += __shfl_xor_sync(0xffffffffu, l1, o);
        }
        float inv0 = 1.f / l0, inv1 = 1.f / l1;

        // ---- O = P . V (V fragments via ldmatrix.trans from kv rows) ----
        float oacc[8][4];
        #pragma unroll
        for (int j = 0; j < 8; j++)
            #pragma unroll
            for (int q = 0; q < 4; q++) oacc[j][q] = 0.f;

        #pragma unroll
        for (int ss = 0; ss < 4; ss++) {
            uint32_t pa[4];
            {
                __half2 h0 = __floats2half2_rn(sacc[2*ss][0]*inv0,   sacc[2*ss][1]*inv0);
                __half2 h1 = __floats2half2_rn(sacc[2*ss][2]*inv1,   sacc[2*ss][3]*inv1);
                __half2 h2 = __floats2half2_rn(sacc[2*ss+1][0]*inv0, sacc[2*ss+1][1]*inv0);
                __half2 h3 = __floats2half2_rn(sacc[2*ss+1][2]*inv1, sacc[2*ss+1][3]*inv1);
                pa[0] = *reinterpret_cast<uint32_t*>(&h0);
                pa[1] = *reinterpret_cast<uint32_t*>(&h1);
                pa[2] = *reinterpret_cast<uint32_t*>(&h2);
                pa[3] = *reinterpret_cast<uint32_t*>(&h3);
            }
            #pragma unroll
            for (int ng = 0; ng < 4; ng++) {
                uint32_t bv[4];
                int sr = ss*16 + (lane & 7) + ((lane >> 3) & 1)*8;
                int sc = h*64 + ng*16 + ((lane >> 4) & 1)*8;
                ldsm4t(bv, sb + (uint32_t)(KV_OFF + sr*KV_LD + 192 + sc)*2);
                mma_fp16(oacc[2*ng],     pa, bv[0], bv[1]);
                mma_fp16(oacc[2*ng + 1], pa, bv[2], bv[3]);
            }
        }

        // ---- store O fragments ----
        int g = lane >> 2, t = lane & 3;
        int r0 = g, r1 = g + 8;
        size_t orow0 = ((size_t)(b*128 + wi*4 + (r0 >> 2)))*128 + wj*4 + (r0 & 3);
        size_t orow1 = ((size_t)(b*128 + wi*4 + (r1 >> 2)))*128 + wj*4 + (r1 & 3);
        #pragma unroll
        for (int j = 0; j < 8; j++) {
            int col = h*64 + j*8 + 2*t;
            *reinterpret_cast<__half2*>(O + orow0*192 + col) =
                __floats2half2_rn(oacc[j][0], oacc[j][1]);
            *reinterpret_cast<__half2*>(O + orow1*192 + col) =
                __floats2half2_rn(oacc[j][2], oacc[j][3]);
        }
    }
}

// ---------------- launch ----------------------------------------------------
extern "C" void kernel_launch(void* const* d_in, const int* in_sizes, int n_in,
                              void* d_out, int out_size)
{
    const float* x       = (const float*)d_in[0];
    const float* n1g     = (const float*)d_in[1];
    const float* n1b     = (const float*)d_in[2];
    const float* proj_w  = (const float*)d_in[3];
    const float* proj_b  = (const float*)d_in[4];
    const float* qkv_w   = (const float*)d_in[5];
    const float* qkv_b   = (const float*)d_in[6];
    const float* apw     = (const float*)d_in[7];
    const float* apb     = (const float*)d_in[8];
    const float* n2g     = (const float*)d_in[9];
    const float* n2b     = (const float*)d_in[10];
    const float* w1      = (const float*)d_in[11];
    const float* b1      = (const float*)d_in[12];
    const float* w2      = (const float*)d_in[13];
    const float* b2      = (const float*)d_in[14];
    float* y = (float*)d_out;

    __half *x16, *qkv16, *o16, *yn16, *h16, *wf16, *wa16, *w116, *w216;
    float *b768;
    cudaGetSymbolAddress((void**)&x16,  g_x16);
    cudaGetSymbolAddress((void**)&qkv16, g_qkv);
    cudaGetSymbolAddress((void**)&o16,  g_o);
    cudaGetSymbolAddress((void**)&yn16, g_yn);
    cudaGetSymbolAddress((void**)&h16,  g_h);
    cudaGetSymbolAddress((void**)&wf16, g_wf16);
    cudaGetSymbolAddress((void**)&wa16, g_wa16);
    cudaGetSymbolAddress((void**)&w116, g_w116);
    cudaGetSymbolAddress((void**)&w216, g_w216);
    cudaGetSymbolAddress((void**)&b768, g_b768);

    static bool attr_done = false;
    if (!attr_done) {
        cudaFuncSetAttribute(attn_kernel,
            cudaFuncAttributeMaxDynamicSharedMemorySize, ATT_SMEM);
        cudaFuncSetAttribute(gemm_f16,
            cudaFuncAttributeMaxDynamicSharedMemorySize, GEMMH_SMEM);
        attr_done = true;
    }

    // 0) merged weight conversions + bias concat
    conv_all_kernel<<<(406272 + 255) / 256, 256>>>(
        proj_w, qkv_w, apw, w1, w2, proj_b, qkv_b,
        wf16, wa16, w116, w216, b768);
    // 1) LN1 -> fp16 (window-major rows)
    ln96h_kernel<<<NPIX/8, 256>>>(x, n1g, n1b, x16);
    // 2) fused proj+qkv GEMM: tile0 -> pooled y, tiles1-3 -> qkv fp16
    gemm_f16<<<dim3(4, NPIX/128), 256, GEMMH_SMEM>>>(
        x16, wf16, 96, 768, 3, b768, y, qkv16, nullptr);
    // 3) windowed attention (HMMA flash, cp.async) -> O (fp16)
    attn_kernel<<<NWIN, 128, ATT_SMEM>>>(qkv16, o16);
    // 4) attn-proj GEMM: y += O @ apw + apb
    gemm_f16<<<dim3(1, NPOOL/128), 256, GEMMH_SMEM>>>(
        o16, wa16, 192, 192, 2, apb, y, nullptr, y);
    // 5) LN2 -> fp16
    ln192h_kernel<<<NPOOL/8, 256>>>(y, n2g, n2b, yn16);
    // 6) mlp1 GEMM + gelu -> h (fp16)
    gemm_f16<<<dim3(4, NPOOL/128), 256, GEMMH_SMEM>>>(
        yn16, w116, 192, 768, 1, b1, nullptr, h16, nullptr);
    // 7) mlp2 GEMM + residual add -> y (d_out)
    gemm_f16<<<dim3(1, NPOOL/128), 256, GEMMH_SMEM>>>(
        h16, w216, 768, 192, 2, b2, y, nullptr, y);
}

// round 15
// speedup vs baseline: 1.2589x; 1.0767x over previous
#include <cuda_runtime.h>
#include <cuda_bf16.h>
#include <cuda_fp16.h>
#include <cstdint>
#include <math.h>

// ===========================================================================
// MultiScaleBlock (sm_103 PTX, HMMA mma.sync path).
// All GEMMs fp16 x1. Fused proj+qkv GEMM pools BOTH y (proj) and q in its
// epilogue; k/v go to a dense [win][64][384] buffer. Flash HMMA attention
// cp.asyncs qp+kv, fragment softmax, ldmatrix.trans V.
// ===========================================================================

#define NPIX   (4*256*256)     // 262144
#define NPOOL  (4*128*128)     // 65536
#define NWIN   (4*32*32)       // 4096

// ---------------- scratch (device globals) ----------------------------------
__device__ __half g_x16 [(size_t)NPIX  * 96];    // LN1 out, window-major fp16
__device__ __half g_qp  [(size_t)NPOOL * 192];   // pooled q, window-major quads
__device__ __half g_kv  [(size_t)NPIX  * 384];   // k|v per window row
__device__ __half g_o   [(size_t)NPOOL * 192];   // attention O
__device__ __half g_yn  [(size_t)NPOOL * 192];   // LN2 out
__device__ __half g_h   [(size_t)NPOOL * 768];   // mlp hidden
// weights fp16 [N][K] (transposed); proj+qkv fused into 768 rows
__device__ __half g_wf16[768*96];
__device__ __half g_wa16[192*192];
__device__ __half g_w116[768*192];
__device__ __half g_w216[192*768];
__device__ float  g_b768[768];

// ---------------- helpers ---------------------------------------------------
__device__ __forceinline__ uint32_t smem_u32(const void* p) {
    uint32_t a;
    asm("{ .reg .u64 t; cvta.to.shared.u64 t, %1; cvt.u32.u64 %0, t; }"
        : "=r"(a) : "l"(p));
    return a;
}
__device__ __forceinline__ void cp16(uint32_t s, const void* g) {
    asm volatile("cp.async.ca.shared.global [%0], [%1], 16;"
                 :: "r"(s), "l"(g) : "memory");
}
__device__ __forceinline__ void cp_commit() {
    asm volatile("cp.async.commit_group;" ::: "memory");
}
template<int N>
__device__ __forceinline__ void cp_wait() {
    asm volatile("cp.async.wait_group %0;" :: "n"(N) : "memory");
}
__device__ __forceinline__ void ldsm4(uint32_t* r, uint32_t a) {
    asm volatile("ldmatrix.sync.aligned.m8n8.x4.shared.b16 {%0,%1,%2,%3}, [%4];"
        : "=r"(r[0]), "=r"(r[1]), "=r"(r[2]), "=r"(r[3]) : "r"(a));
}
__device__ __forceinline__ void ldsm4t(uint32_t* r, uint32_t a) {
    asm volatile("ldmatrix.sync.aligned.m8n8.x4.trans.shared.b16 {%0,%1,%2,%3}, [%4];"
        : "=r"(r[0]), "=r"(r[1]), "=r"(r[2]), "=r"(r[3]) : "r"(a));
}
__device__ __forceinline__ void mma_fp16(float* d, const uint32_t* a,
                                         uint32_t b0, uint32_t b1) {
    asm volatile(
        "mma.sync.aligned.m16n8k16.row.col.f32.f16.f16.f32 "
        "{%0,%1,%2,%3}, {%4,%5,%6,%7}, {%8,%9}, {%0,%1,%2,%3};"
        : "+f"(d[0]), "+f"(d[1]), "+f"(d[2]), "+f"(d[3])
        : "r"(a[0]), "r"(a[1]), "r"(a[2]), "r"(a[3]), "r"(b0), "r"(b1));
}
__device__ __forceinline__ float gelu_exact(float v) {
    return 0.5f * v * (1.0f + erff(v * 0.70710678118654752f));
}
__device__ __forceinline__ size_t quad_to_prow(size_t g) {
    int t2 = (int)(g & 15);
    int wj = (int)((g >> 4) & 31);
    int wi = (int)((g >> 9) & 31);
    int b  = (int)(g >> 14);
    return ((size_t)(b * 128 + wi * 4 + (t2 >> 2))) * 128 + wj * 4 + (t2 & 3);
}

// ======== fp16 x1 GEMM, BM=128 BN=192 BK=32, 3-stage, 2 CTA/SM ==============
// epi: 1 = gelu -> fp16; 2 = +bias +addsrc -> fp32;
//      3 = fused: bn==0 -> pooled y (fp32); bn==1 -> pooled q fp16 (qp);
//                 bn>=2 -> k|v fp16 into Ckv [row][col-384], ld 384
#define LDAH     40
#define SAH      0
#define SBH      (128*LDAH*2)               // 10240
#define STAGEH   (SBH + 192*LDAH*2)         // 25600
#define GEMMH_SMEM (3*STAGEH)               // 76800

__global__ __launch_bounds__(256, 2) void gemm_f16(
    const __half* __restrict__ A, const __half* __restrict__ B,
    int K, int N, int epi,
    const float* __restrict__ bias,
    float* __restrict__ Cf, __half* __restrict__ Ch,
    __half* __restrict__ Ckv,
    const float* __restrict__ addsrc)
{
    extern __shared__ char smem[];
    const uint32_t sb = smem_u32(smem);
    const int tid = threadIdx.x, lane = tid & 31, warp = tid >> 5;
    const int wm = (warp >> 1) * 32;
    const int wn = (warp & 1) * 96;
    const size_t bm = (size_t)blockIdx.y * 128;
    const size_t bn = (size_t)blockIdx.x * 192;
    const int C = K >> 5;

    const __half* AB = A + bm * K;
    const __half* BB = B + bn * K;

    float acc[2][12][4];
    #pragma unroll
    for (int i = 0; i < 2; i++)
        #pragma unroll
        for (int j = 0; j < 12; j++)
            #pragma unroll
            for (int q = 0; q < 4; q++) acc[i][j][q] = 0.f;

    auto load_stage = [&](int s, int c) {
        const uint32_t st = sb + (uint32_t)s * STAGEH;
        const size_t k0 = (size_t)c * 32;
        #pragma unroll
        for (int i = tid; i < 512; i += 256) {
            int r = i >> 2, q = i & 3;
            cp16(st + SAH + (uint32_t)(r * LDAH + q * 8) * 2,
                 AB + (size_t)r * K + k0 + q * 8);
        }
        #pragma unroll
        for (int i = tid; i < 768; i += 256) {
            int r = i >> 2, q = i & 3;
            cp16(st + SBH + (uint32_t)(r * LDAH + q * 8) * 2,
                 BB + (size_t)r * K + k0 + q * 8);
        }
        cp_commit();
    };

    auto compute_stage = [&](int s) {
        const uint32_t st = sb + (uint32_t)s * STAGEH;
        #pragma unroll
        for (int k16 = 0; k16 < 2; k16++) {
            uint32_t ah[2][4];
            #pragma unroll
            for (int mi = 0; mi < 2; mi++) {
                int row = wm + mi * 16 + (lane & 15);
                int col = k16 * 16 + (lane >> 4) * 8;
                ldsm4(ah[mi], st + SAH + (uint32_t)(row * LDAH + col) * 2);
            }
            #pragma unroll
            for (int ng = 0; ng < 6; ng++) {
                uint32_t bh[4];
                int nr = wn + ng * 16 + (lane & 7) + ((lane >> 4) & 1) * 8;
                int bc = k16 * 16 + ((lane >> 3) & 1) * 8;
                ldsm4(bh, st + SBH + (uint32_t)(nr * LDAH + bc) * 2);
                #pragma unroll
                for (int mi = 0; mi < 2; mi++) {
                    #pragma unroll
                    for (int sub = 0; sub < 2; sub++)
                        mma_fp16(acc[mi][ng * 2 + sub], ah[mi], bh[2*sub], bh[2*sub+1]);
                }
            }
        }
    };

    load_stage(0, 0);
    load_stage(1, 1);
    for (int c = 0; c < C; c++) {
        if (c + 1 < C) { cp_wait<1>(); } else { cp_wait<0>(); }
        __syncthreads();
        if (c + 2 < C) load_stage((c + 2) % 3, c + 2);
        compute_stage(c % 3);
        __syncthreads();
    }

    #pragma unroll
    for (int mi = 0; mi < 2; mi++) {
        #pragma unroll
        for (int nj = 0; nj < 12; nj++) {
            size_t row0 = bm + wm + mi * 16 + (lane >> 2);
            size_t col  = bn + wn + nj * 8 + 2 * (lane & 3);
            float b0 = bias[col], b1 = bias[col + 1];
            float v00 = acc[mi][nj][0] + b0, v01 = acc[mi][nj][1] + b1;
            float v10 = acc[mi][nj][2] + b0, v11 = acc[mi][nj][3] + b1;
            if (epi == 1) {
                v00 = gelu_exact(v00); v01 = gelu_exact(v01);
                v10 = gelu_exact(v10); v11 = gelu_exact(v11);
                *reinterpret_cast<__half2*>(Ch + row0 * N + col)       = __floats2half2_rn(v00, v01);
                *reinterpret_cast<__half2*>(Ch + (row0 + 8) * N + col) = __floats2half2_rn(v10, v11);
            } else if (epi == 2) {
                const float2 a0 = *reinterpret_cast<const float2*>(addsrc + row0 * N + col);
                const float2 a1 = *reinterpret_cast<const float2*>(addsrc + (row0 + 8) * N + col);
                *reinterpret_cast<float2*>(Cf + row0 * N + col)       = make_float2(v00 + a0.x, v01 + a0.y);
                *reinterpret_cast<float2*>(Cf + (row0 + 8) * N + col) = make_float2(v10 + a1.x, v11 + a1.y);
            } else {  // epi == 3
                if (bn < 384) {
                    // pooled output (proj -> y fp32, q -> qp fp16)
                    float p00 = fmaxf(v00, __shfl_xor_sync(0xffffffffu, v00, 4));
                    p00 = fmaxf(p00, __shfl_xor_sync(0xffffffffu, p00, 8));
                    float p01 = fmaxf(v01, __shfl_xor_sync(0xffffffffu, v01, 4));
                    p01 = fmaxf(p01, __shfl_xor_sync(0xffffffffu, p01, 8));
                    float p10 = fmaxf(v10, __shfl_xor_sync(0xffffffffu, v10, 4));
                    p10 = fmaxf(p10, __shfl_xor_sync(0xffffffffu, p10, 8));
                    float p11 = fmaxf(v11, __shfl_xor_sync(0xffffffffu, v11, 4));
                    p11 = fmaxf(p11, __shfl_xor_sync(0xffffffffu, p11, 8));
                    if ((lane & 12) == 0) {
                        size_t q0 = row0 >> 2, q1 = (row0 + 8) >> 2;
                        if (bn == 0) {
                            size_t pr0 = quad_to_prow(q0);
                            size_t pr1 = quad_to_prow(q1);
                            *reinterpret_cast<float2*>(Cf + pr0 * 192 + col) = make_float2(p00, p01);
                            *reinterpret_cast<float2*>(Cf + pr1 * 192 + col) = make_float2(p10, p11);
                        } else {
                            size_t qc = col - 192;
                            *reinterpret_cast<__half2*>(Ch + q0 * 192 + qc) = __floats2half2_rn(p00, p01);
                            *reinterpret_cast<__half2*>(Ch + q1 * 192 + qc) = __floats2half2_rn(p10, p11);
                        }
                    }
                } else {
                    // k | v -> dense kv buffer, ld 384
                    size_t kc = col - 384;
                    *reinterpret_cast<__half2*>(Ckv + row0 * 384 + kc)       = __floats2half2_rn(v00, v01);
                    *reinterpret_cast<__half2*>(Ckv + (row0 + 8) * 384 + kc) = __floats2half2_rn(v10, v11);
                }
            }
        }
    }
}

// ---------------- LN1 -> fp16, window-major permuted rows -------------------
__global__ __launch_bounds__(256) void ln96h_kernel(
    const float* __restrict__ x, const float* __restrict__ g,
    const float* __restrict__ bb, __half* __restrict__ out)
{
    int row  = blockIdx.x * 8 + (threadIdx.x >> 5);
    int lane = threadIdx.x & 31;
    const float* p = x + (size_t)row * 96;
    float v0 = p[lane], v1 = p[lane+32], v2 = p[lane+64];
    float s = v0 + v1 + v2;
    #pragma unroll
    for (int o = 16; o > 0; o >>= 1) s += __shfl_xor_sync(0xffffffffu, s, o);
    float mean = s * (1.0f/96.0f);
    float d0 = v0-mean, d1 = v1-mean, d2 = v2-mean;
    float vs = d0*d0 + d1*d1 + d2*d2;
    #pragma unroll
    for (int o = 16; o > 0; o >>= 1) vs += __shfl_xor_sync(0xffffffffu, vs, o);
    float inv = rsqrtf(vs * (1.0f/96.0f) + 1e-6f);
    int wpix = row & 255, hpix = (row >> 8) & 255, b = row >> 16;
    int wi = hpix >> 3, r = hpix & 7, wj = wpix >> 3, c = wpix & 7;
    int t2 = (r >> 1) * 4 + (c >> 1);
    int dq = (r & 1) * 2 + (c & 1);
    size_t wrow = ((((size_t)b * 32 + wi) * 32 + wj) * 16 + t2) * 4 + dq;
    __half* q = out + wrow * 96;
    q[lane]    = __float2half(d0*inv*g[lane]    + bb[lane]);
    q[lane+32] = __float2half(d1*inv*g[lane+32] + bb[lane+32]);
    q[lane+64] = __float2half(d2*inv*g[lane+64] + bb[lane+64]);
}

// ---------------- LN2 -> fp16 -----------------------------------------------
__global__ __launch_bounds__(256) void ln192h_kernel(
    const float* __restrict__ x, const float* __restrict__ g,
    const float* __restrict__ bb, __half* __restrict__ out)
{
    int row  = blockIdx.x * 8 + (threadIdx.x >> 5);
    int lane = threadIdx.x & 31;
    const float* p = x + (size_t)row * 192;
    float v[6];
    float s = 0.f;
    #pragma unroll
    for (int i = 0; i < 6; i++) { v[i] = p[lane + 32*i]; s += v[i]; }
    #pragma unroll
    for (int o = 16; o > 0; o >>= 1) s += __shfl_xor_sync(0xffffffffu, s, o);
    float mean = s * (1.0f/192.0f);
    float vs = 0.f;
    #pragma unroll
    for (int i = 0; i < 6; i++) { v[i] -= mean; vs += v[i]*v[i]; }
    #pragma unroll
    for (int o = 16; o > 0; o >>= 1) vs += __shfl_xor_sync(0xffffffffu, vs, o);
    float inv = rsqrtf(vs * (1.0f/192.0f) + 1e-6f);
    __half* q = out + (size_t)row * 192;
    #pragma unroll
    for (int i = 0; i < 6; i++)
        q[lane + 32*i] = __float2half(v[i]*inv*g[lane + 32*i] + bb[lane + 32*i]);
}

// ---------------- merged weight conversion + bias concat --------------------
__global__ __launch_bounds__(256) void conv_all_kernel(
    const float* __restrict__ proj_w, const float* __restrict__ qkv_w,
    const float* __restrict__ apw, const float* __restrict__ w1,
    const float* __restrict__ w2,
    const float* __restrict__ proj_b, const float* __restrict__ qkv_b,
    __half* __restrict__ wf16, __half* __restrict__ wa16,
    __half* __restrict__ w116, __half* __restrict__ w216,
    float* __restrict__ b768)
{
    int i = blockIdx.x * 256 + threadIdx.x;
    if (i < 405504) {
        const float* W; __half* H; int K, N, j;
        if (i < 18432)       { W = proj_w; H = wf16;         K = 96;  N = 192; j = i; }
        else if (i < 73728)  { W = qkv_w;  H = wf16 + 18432; K = 96;  N = 576; j = i - 18432; }
        else if (i < 110592) { W = apw;    H = wa16;         K = 192; N = 192; j = i - 73728; }
        else if (i < 258048) { W = w1;     H = w116;         K = 192; N = 768; j = i - 110592; }
        else                 { W = w2;     H = w216;         K = 768; N = 192; j = i - 258048; }
        int n = j / K, k = j % K;
        H[j] = __float2half(W[(size_t)k * N + n]);
    } else if (i < 406272) {
        int j = i - 405504;
        b768[j] = (j < 192) ? proj_b[j] : qkv_b[j - 192];
    }
}

// ---------------- flash HMMA windowed attention (cp.async qp+kv) ------------
// 128 threads/window, 4 CTAs/SM.
// smem (halves): qp [16][200] @0 | kv [64][392] @3200 (k 0..191 | v 192..383)
#define QP_OFF  0
#define KV_OFF  3200
#define KV_LD   392
#define ATT_SMEM ((3200 + 64*KV_LD) * 2)    // 56576 B

__global__ __launch_bounds__(128, 4) void attn_kernel(
    const __half* __restrict__ QP, const __half* __restrict__ KV,
    __half* __restrict__ O)
{
    extern __shared__ char smem[];
    const uint32_t sb = smem_u32(smem);

    int w = blockIdx.x;
    int b = w >> 10, wi = (w >> 5) & 31, wj = w & 31;
    int tid = threadIdx.x;
    const __half* qp_g = QP + (size_t)w * 16 * 192;
    const __half* kv_g = KV + (size_t)w * 64 * 384;

    // ---- cp.async pooled q: 16 rows x 24 chunks ----
    for (int i = tid; i < 384; i += 128) {
        int t2 = i / 24, c = i % 24;
        cp16(sb + (uint32_t)(QP_OFF + t2*200)*2 + c*16,
             qp_g + (size_t)t2*192 + c*8);
    }
    // ---- cp.async kv: 64 rows x 48 chunks ----
    for (int i = tid; i < 64*48; i += 128) {
        int s = i / 48, c = i % 48;
        cp16(sb + (uint32_t)(KV_OFF + s*KV_LD)*2 + c*16,
             kv_g + (size_t)s*384 + c*8);
    }
    cp_commit();
    cp_wait<0>();
    __syncthreads();

    const int warp = tid >> 5, lane = tid & 31;
    if (warp < 3) {
        const int h = warp;
        // ---- S = Qp . K^T ----
        float sacc[8][4];
        #pragma unroll
        for (int j = 0; j < 8; j++)
            #pragma unroll
            for (int q = 0; q < 4; q++) sacc[j][q] = 0.f;

        #pragma unroll
        for (int kk = 0; kk < 4; kk++) {
            uint32_t aq[4];
            ldsm4(aq, sb + (uint32_t)(QP_OFF + (lane & 15)*200 + h*64 + kk*16 + (lane >> 4)*8)*2);
            #pragma unroll
            for (int ng = 0; ng < 4; ng++) {
                uint32_t bk[4];
                int nr = ng*16 + (lane & 7) + ((lane >> 4) & 1)*8;
                int bc = h*64 + kk*16 + ((lane >> 3) & 1)*8;
                ldsm4(bk, sb + (uint32_t)(KV_OFF + nr*KV_LD + bc)*2);
                mma_fp16(sacc[2*ng],     aq, bk[0], bk[1]);
                mma_fp16(sacc[2*ng + 1], aq, bk[2], bk[3]);
            }
        }

        // ---- fragment softmax ----
        float mx0 = -1e30f, mx1 = -1e30f;
        #pragma unroll
        for (int j = 0; j < 8; j++) {
            mx0 = fmaxf(mx0, fmaxf(sacc[j][0], sacc[j][1]));
            mx1 = fmaxf(mx1, fmaxf(sacc[j][2], sacc[j][3]));
        }
        #pragma unroll
        for (int o = 1; o < 4; o <<= 1) {
            mx0 = fmaxf(mx0, __shfl_xor_sync(0xffffffffu, mx0, o));
            mx1 = fmaxf(mx1, __shfl_xor_sync(0xffffffffu, mx1, o));
        }
        float l0 = 0.f, l1 = 0.f;
        #pragma unroll
        for (int j = 0; j < 8; j++) {
            sacc[j][0] = __expf((sacc[j][0] - mx0) * 0.125f);
            sacc[j][1] = __expf((sacc[j][1] - mx0) * 0.125f);
            sacc[j][2] = __expf((sacc[j][2] - mx1) * 0.125f);
            sacc[j][3] = __expf((sacc[j][3] - mx1) * 0.125f);
            l0 += sacc[j][0] + sacc[j][1];
            l1 += sacc[j][2] + sacc[j][3];
        }
        #pragma unroll
        for (int o = 1; o < 4; o <<= 1) {
            l0 += __shfl_xor_sync(0xffffffffu, l0, o);
            l1 += __shfl_xor_sync(0xffffffffu, l1, o);
        }
        float inv0 = 1.f / l0, inv1 = 1.f / l1;

        // ---- O = P . V (V fragments via ldmatrix.trans) ----
        float oacc[8][4];
        #pragma unroll
        for (int j = 0; j < 8; j++)
            #pragma unroll
            for (int q = 0; q < 4; q++) oacc[j][q] = 0.f;

        #pragma unroll
        for (int ss = 0; ss < 4; ss++) {
            uint32_t pa[4];
            {
                __half2 h0 = __floats2half2_rn(sacc[2*ss][0]*inv0,   sacc[2*ss][1]*inv0);
                __half2 h1 = __floats2half2_rn(sacc[2*ss][2]*inv1,   sacc[2*ss][3]*inv1);
                __half2 h2 = __floats2half2_rn(sacc[2*ss+1][0]*inv0, sacc[2*ss+1][1]*inv0);
                __half2 h3 = __floats2half2_rn(sacc[2*ss+1][2]*inv1, sacc[2*ss+1][3]*inv1);
                pa[0] = *reinterpret_cast<uint32_t*>(&h0);
                pa[1] = *reinterpret_cast<uint32_t*>(&h1);
                pa[2] = *reinterpret_cast<uint32_t*>(&h2);
                pa[3] = *reinterpret_cast<uint32_t*>(&h3);
            }
            #pragma unroll
            for (int ng = 0; ng < 4; ng++) {
                uint32_t bv[4];
                int sr = ss*16 + (lane & 7) + ((lane >> 3) & 1)*8;
                int sc = h*64 + ng*16 + ((lane >> 4) & 1)*8;
                ldsm4t(bv, sb + (uint32_t)(KV_OFF + sr*KV_LD + 192 + sc)*2);
                mma_fp16(oacc[2*ng],     pa, bv[0], bv[1]);
                mma_fp16(oacc[2*ng + 1], pa, bv[2], bv[3]);
            }
        }

        // ---- store O fragments ----
        int g = lane >> 2, t = lane & 3;
        int r0 = g, r1 = g + 8;
        size_t orow0 = ((size_t)(b*128 + wi*4 + (r0 >> 2)))*128 + wj*4 + (r0 & 3);
        size_t orow1 = ((size_t)(b*128 + wi*4 + (r1 >> 2)))*128 + wj*4 + (r1 & 3);
        #pragma unroll
        for (int j = 0; j < 8; j++) {
            int col = h*64 + j*8 + 2*t;
            *reinterpret_cast<__half2*>(O + orow0*192 + col) =
                __floats2half2_rn(oacc[j][0], oacc[j][1]);
            *reinterpret_cast<__half2*>(O + orow1*192 + col) =
                __floats2half2_rn(oacc[j][2], oacc[j][3]);
        }
    }
}

// ---------------- launch ----------------------------------------------------
extern "C" void kernel_launch(void* const* d_in, const int* in_sizes, int n_in,
                              void* d_out, int out_size)
{
    const float* x       = (const float*)d_in[0];
    const float* n1g     = (const float*)d_in[1];
    const float* n1b     = (const float*)d_in[2];
    const float* proj_w  = (const float*)d_in[3];
    const float* proj_b  = (const float*)d_in[4];
    const float* qkv_w   = (const float*)d_in[5];
    const float* qkv_b   = (const float*)d_in[6];
    const float* apw     = (const float*)d_in[7];
    const float* apb     = (const float*)d_in[8];
    const float* n2g     = (const float*)d_in[9];
    const float* n2b     = (const float*)d_in[10];
    const float* w1      = (const float*)d_in[11];
    const float* b1      = (const float*)d_in[12];
    const float* w2      = (const float*)d_in[13];
    const float* b2      = (const float*)d_in[14];
    float* y = (float*)d_out;

    __half *x16, *qp16, *kv16, *o16, *yn16, *h16, *wf16, *wa16, *w116, *w216;
    float *b768;
    cudaGetSymbolAddress((void**)&x16,  g_x16);
    cudaGetSymbolAddress((void**)&qp16, g_qp);
    cudaGetSymbolAddress((void**)&kv16, g_kv);
    cudaGetSymbolAddress((void**)&o16,  g_o);
    cudaGetSymbolAddress((void**)&yn16, g_yn);
    cudaGetSymbolAddress((void**)&h16,  g_h);
    cudaGetSymbolAddress((void**)&wf16, g_wf16);
    cudaGetSymbolAddress((void**)&wa16, g_wa16);
    cudaGetSymbolAddress((void**)&w116, g_w116);
    cudaGetSymbolAddress((void**)&w216, g_w216);
    cudaGetSymbolAddress((void**)&b768, g_b768);

    static bool attr_done = false;
    if (!attr_done) {
        cudaFuncSetAttribute(attn_kernel,
            cudaFuncAttributeMaxDynamicSharedMemorySize, ATT_SMEM);
        cudaFuncSetAttribute(gemm_f16,
            cudaFuncAttributeMaxDynamicSharedMemorySize, GEMMH_SMEM);
        attr_done = true;
    }

    // 0) merged weight conversions + bias concat
    conv_all_kernel<<<(406272 + 255) / 256, 256>>>(
        proj_w, qkv_w, apw, w1, w2, proj_b, qkv_b,
        wf16, wa16, w116, w216, b768);
    // 1) LN1 -> fp16 (window-major rows)
    ln96h_kernel<<<NPIX/8, 256>>>(x, n1g, n1b, x16);
    // 2) fused proj+qkv GEMM: pooled y + pooled qp + dense kv
    gemm_f16<<<dim3(4, NPIX/128), 256, GEMMH_SMEM>>>(
        x16, wf16, 96, 768, 3, b768, y, qp16, kv16, nullptr);
    // 3) windowed attention (HMMA flash) -> O (fp16)
    attn_kernel<<<NWIN, 128, ATT_SMEM>>>(qp16, kv16, o16);
    // 4) attn-proj GEMM: y += O @ apw + apb
    gemm_f16<<<dim3(1, NPOOL/128), 256, GEMMH_SMEM>>>(
        o16, wa16, 192, 192, 2, apb, y, nullptr, nullptr, y);
    // 5) LN2 -> fp16
    ln192h_kernel<<<NPOOL/8, 256>>>(y, n2g, n2b, yn16);
    // 6) mlp1 GEMM + gelu -> h (fp16)
    gemm_f16<<<dim3(4, NPOOL/128), 256, GEMMH_SMEM>>>(
        yn16, w116, 192, 768, 1, b1, nullptr, h16, nullptr, nullptr);
    // 7) mlp2 GEMM + residual add -> y (d_out)
    gemm_f16<<<dim3(1, NPOOL/128), 256, GEMMH_SMEM>>>(
        h16, w216, 768, 192, 2, b2, y, nullptr, nullptr, y);
}